// round 9
// baseline (speedup 1.0000x reference)
#include <cuda_runtime.h>

// CapsuleLayer: x[B,I,D] fp32, W[I,O,D,K] fp32 -> v[B,O,K] fp32
// B=64, I=2048, D=8, O=32, K=16, 3 routing rounds.
// Routing logits linear in v => each round is one fused sweep over i.
// Round 9: 1 b per thread (u/s/V register state halved -> <=85 regs) and
// __launch_bounds__(256,3): 3 blocks/SM = 24 warps = 6/SMSP to hide the
// LDS/shuffle/barrier latency that held issue at 37% with 4 warps/SMSP.

#define BB 64
#define II 2048
#define DD 8
#define OO 32
#define KK 16
#define BG 8             // b's per block (1 per thread)
#define GX 55            // i-blocks; grid = 55 x 8 = 440 ~ 148 SM x 3
#define NBUF 3
#define SVOL (BB*OO*KK)  // 32768

#define WROWF 132                 // padded floats per o-row
#define WSLABF (OO*WROWF)         // 4224 floats (one i)
#define XROWF 12
#define XSLABF (BG*XROWF)         // 96 floats
#define SLABF  (WSLABF + XSLABF)  // 4320 floats
#define AG_OFF (NBUF*SLABF)       // 12960 floats
#define AGROW  33
#define SMEM_BYTES ((AG_OFF + BG*AGROW) * 4)   // 52896 B (x3 = 159KB/SM)

__device__ float g_part[GX * SVOL];  // per-i-block partial s (7.2 MB)
__device__ float g_vsum[SVOL];       // running sum of squashed v's

// ---------- packed f32x2 helpers ----------
__device__ __forceinline__ unsigned long long pk2(float lo, float hi) {
    unsigned long long r;
    asm("mov.b64 %0, {%1, %2};" : "=l"(r) : "f"(lo), "f"(hi));
    return r;
}
__device__ __forceinline__ void upk2(unsigned long long v, float& lo, float& hi) {
    asm("mov.b64 {%0, %1}, %2;" : "=f"(lo), "=f"(hi) : "l"(v));
}
__device__ __forceinline__ unsigned long long fma2(unsigned long long a,
                                                   unsigned long long b,
                                                   unsigned long long c) {
    unsigned long long d;
    asm("fma.rn.f32x2 %0, %1, %2, %3;" : "=l"(d) : "l"(a), "l"(b), "l"(c));
    return d;
}

// ---------- cp.async helpers ----------
__device__ __forceinline__ void cp16(unsigned dst_smem, const void* src) {
    asm volatile("cp.async.cg.shared.global [%0], [%1], 16;"
                 :: "r"(dst_smem), "l"(src));
}
__device__ __forceinline__ void cp_commit() {
    asm volatile("cp.async.commit_group;");
}
template<int N>
__device__ __forceinline__ void cp_wait() {
    asm volatile("cp.async.wait_group %0;" :: "n"(N) : "memory");
}

// Stage one i (W tile + x column) into buffer `buf`. One commit group.
// 256 threads: W = 1024 float4 chunks (4/thread), x = 16 chunks (thr 0..15).
__device__ __forceinline__ void fill_slab(unsigned sm_addr,
                                          const float* __restrict__ W,
                                          const float* __restrict__ x,
                                          int i, int buf, int t, int bg) {
#pragma unroll
    for (int r = 0; r < 4; r++) {
        int c = t + r * 256;
        int o = c >> 5, w16 = c & 31;
        const float* src = W + ((size_t)i * OO + o) * (DD * KK) + w16 * 4;
        unsigned dst = sm_addr + (unsigned)((buf * SLABF + o * WROWF + w16 * 4) * 4);
        cp16(dst, src);
    }
    if (t < BG * 2) {
        int b = t >> 1, half = t & 1;
        const float* src = x + ((size_t)(bg * BG + b) * II + i) * DD + half * 4;
        unsigned dst = sm_addr +
            (unsigned)((buf * SLABF + WSLABF + b * XROWF + half * 4) * 4);
        cp16(dst, src);
    }
    cp_commit();
}

// Fused routing pass. 256 threads: t = o*8 + tb; thread handles b = bg*8+tb.
// Warp = 4 o x 8 tb -> W smem reads 8-way amortized across tb lanes.
template<bool FIRST>
__global__ __launch_bounds__(256, 3)
void pass_kernel(const float* __restrict__ x, const float* __restrict__ W) {
    extern __shared__ float sm[];
    const unsigned sm_addr = (unsigned)__cvta_generic_to_shared(sm);
    float* ag = sm + AG_OFF;

    const int t  = threadIdx.x;
    const int o  = t >> 3;
    const int tb = t & 7;
    const int bg = blockIdx.y;
    const int b  = bg * BG + tb;

    // variable i-range: block bx handles [ib, ie)
    const int bx = blockIdx.x;
    const int ib = (bx * II) / GX;
    const int ie = ((bx + 1) * II) / GX;
    const int cnt = ie - ib;

    fill_slab(sm_addr, W, x, ib,     0, t, bg);
    fill_slab(sm_addr, W, x, ib + 1, 1, t, bg);

    unsigned long long V2[8];
    if (!FIRST) {
        const ulonglong2* vp =
            reinterpret_cast<const ulonglong2*>(g_vsum + ((size_t)b * OO + o) * KK);
#pragma unroll
        for (int j = 0; j < 4; j++) {
            ulonglong2 q = vp[j]; V2[2*j] = q.x; V2[2*j+1] = q.y;
        }
    }

    unsigned long long s2acc[8];
#pragma unroll
    for (int j = 0; j < 8; j++) s2acc[j] = 0ull;

    for (int s = 0; s < cnt; s++) {
        if (s + 1 < cnt) cp_wait<1>(); else cp_wait<0>();
        __syncthreads();   // slab s resident; all warps done with slab s-1
        if (s + 2 < cnt)
            fill_slab(sm_addr, W, x, ib + s + 2, (s + 2) % NBUF, t, bg);

        const float* slab = sm + (s % NBUF) * SLABF;

        float xf[8];
        {
            const float4* xr = reinterpret_cast<const float4*>(
                slab + WSLABF + tb * XROWF);
            float4 a0 = xr[0], a1 = xr[1];
            xf[0]=a0.x; xf[1]=a0.y; xf[2]=a0.z; xf[3]=a0.w;
            xf[4]=a1.x; xf[5]=a1.y; xf[6]=a1.z; xf[7]=a1.w;
        }

        unsigned long long u2[8];
#pragma unroll
        for (int j = 0; j < 8; j++) u2[j] = 0ull;

        const float* wrow = slab + o * WROWF;
#pragma unroll
        for (int d = 0; d < DD; d++) {
            const ulonglong2* wp = reinterpret_cast<const ulonglong2*>(wrow + d * 16);
            unsigned long long x2 = pk2(xf[d], xf[d]);
            ulonglong2 q0 = wp[0], q1 = wp[1];
            u2[0] = fma2(x2, q0.x, u2[0]);
            u2[1] = fma2(x2, q0.y, u2[1]);
            u2[2] = fma2(x2, q1.x, u2[2]);
            u2[3] = fma2(x2, q1.y, u2[3]);
            ulonglong2 q2 = wp[2], q3 = wp[3];
            u2[4] = fma2(x2, q2.x, u2[4]);
            u2[5] = fma2(x2, q2.y, u2[5]);
            u2[6] = fma2(x2, q3.x, u2[6]);
            u2[7] = fma2(x2, q3.y, u2[7]);
        }

        unsigned long long c2;
        if (FIRST) {
            c2 = pk2(1.0f / OO, 1.0f / OO);
        } else {
            // agreement = u . Vsum
            unsigned long long acc = 0ull;
#pragma unroll
            for (int j = 0; j < 8; j++) acc = fma2(u2[j], V2[j], acc);
            float al, ah;
            upk2(acc, al, ah);
            ag[tb * AGROW + o] = al + ah;
            __syncthreads();                 // barrier 1: agr visible

            // warp w (8 warps): softmax of b-row w (lane = o). No max-subtract:
            // |agr| <= |u||Vsum| = O(1), exp safe in fp32.
            {
                int w = t >> 5, lane = t & 31;
                float e0 = __expf(ag[w * AGROW + lane]);
                float s0 = e0;
#pragma unroll
                for (int st = 16; st > 0; st >>= 1)
                    s0 += __shfl_xor_sync(0xffffffffu, s0, st);
                ag[w * AGROW + lane] = __fdividef(e0, s0);
            }
            __syncthreads();                 // barrier 2: c visible

            float c = ag[tb * AGROW + o];
            c2 = pk2(c, c);
        }

#pragma unroll
        for (int j = 0; j < 8; j++) s2acc[j] = fma2(c2, u2[j], s2acc[j]);
    }

    ulonglong2* pp = reinterpret_cast<ulonglong2*>(
        g_part + ((size_t)bx * SVOL + ((size_t)b * OO + o) * KK));
    pp[0] = make_ulonglong2(s2acc[0], s2acc[1]);
    pp[1] = make_ulonglong2(s2acc[2], s2acc[3]);
    pp[2] = make_ulonglong2(s2acc[4], s2acc[5]);
    pp[3] = make_ulonglong2(s2acc[6], s2acc[7]);
}

// Reduce partials over GX=55 slabs (4 chains + 3 tail), squash over K=16.
// phase 0: vsum = v ; phase 1: vsum += v ; phase 2: out = v
__global__ void squash_kernel(float* __restrict__ out, int phase) {
    int idx = blockIdx.x * 256 + threadIdx.x;   // (b*O+o)*K + k
    float a0 = 0.f, a1 = 0.f, a2 = 0.f, a3 = 0.f;
#pragma unroll
    for (int p = 0; p + 4 <= GX; p += 4) {      // p = 0..48, covers 0..51
        a0 += g_part[(size_t)(p + 0) * SVOL + idx];
        a1 += g_part[(size_t)(p + 1) * SVOL + idx];
        a2 += g_part[(size_t)(p + 2) * SVOL + idx];
        a3 += g_part[(size_t)(p + 3) * SVOL + idx];
    }
    a0 += g_part[(size_t)52 * SVOL + idx];
    a1 += g_part[(size_t)53 * SVOL + idx];
    a2 += g_part[(size_t)54 * SVOL + idx];
    float s = (a0 + a1) + (a2 + a3);

    float s2 = s * s;
    s2 += __shfl_xor_sync(0xffffffffu, s2, 1);
    s2 += __shfl_xor_sync(0xffffffffu, s2, 2);
    s2 += __shfl_xor_sync(0xffffffffu, s2, 4);
    s2 += __shfl_xor_sync(0xffffffffu, s2, 8);

    float scale = s2 / ((1.0f + s2) * sqrtf(s2 + 1e-7f));
    float v = scale * s;

    if (phase == 0)      g_vsum[idx] = v;
    else if (phase == 1) g_vsum[idx] += v;
    else                 out[idx] = v;
}

// No-op: keeps ncu's -s 5 -c 1 capture window on pass#3 (softmax pass).
__global__ void dummy_kernel() {}

extern "C" void kernel_launch(void* const* d_in, const int* in_sizes, int n_in,
                              void* d_out, int out_size) {
    const float* a0 = (const float*)d_in[0];
    const float* a1 = (const float*)d_in[1];
    const float* x;
    const float* W;
    if (in_sizes[0] == BB * II * DD) { x = a0; W = a1; }
    else                             { x = a1; W = a0; }
    float* out = (float*)d_out;

    cudaFuncSetAttribute(pass_kernel<true>,
                         cudaFuncAttributeMaxDynamicSharedMemorySize, SMEM_BYTES);
    cudaFuncSetAttribute(pass_kernel<false>,
                         cudaFuncAttributeMaxDynamicSharedMemorySize, SMEM_BYTES);

    dim3 pg(GX, BB / BG);          // (55, 8) = 440 blocks ~ 148 SM x 3
    const int rb = SVOL / 256;     // 128 blocks for squash

    dummy_kernel<<<1, 32>>>();                           // #1 (aligns capture)

    pass_kernel<true><<<pg, 256, SMEM_BYTES>>>(x, W);    // #2: s0 (uniform c)
    squash_kernel<<<rb, 256>>>(out, 0);                  // #3: v0 -> Vsum

    pass_kernel<false><<<pg, 256, SMEM_BYTES>>>(x, W);   // #4: s1 (vs v0)
    squash_kernel<<<rb, 256>>>(out, 1);                  // #5: Vsum += v1

    pass_kernel<false><<<pg, 256, SMEM_BYTES>>>(x, W);   // #6: s2 (profiled)
    squash_kernel<<<rb, 256>>>(out, 2);                  // #7: v2 = output
}

// round 10
// speedup vs baseline: 1.3309x; 1.3309x over previous
#include <cuda_runtime.h>

// CapsuleLayer: x[B,I,D] fp32, W[I,O,D,K] fp32 -> v[B,O,K] fp32
// B=64, I=2048, D=8, O=32, K=16, 3 routing rounds.
// Routing logits linear in v => each round is one fused sweep over i.
// Round 10: R8 base (proven best: 2b/thread W amortization, 256thr x 2/SM,
// grid 74x4 = one perfect wave) + barrier merge: the slab-cycle barrier is
// folded into softmax barrier2, so softmax passes run 2 barriers/i (was 3).

#define BB 64
#define II 2048
#define DD 8
#define OO 32
#define KK 16
#define BG 16            // b's per block (2 per thread)
#define GX 74            // i-blocks; grid = 74 x 4 = 296 = 148 SMs x 2
#define NBUF 3
#define SVOL (BB*OO*KK)  // 32768

#define WROWF 132                 // padded floats per o-row
#define WSLABF (OO*WROWF)         // 4224 floats (one i)
#define XROWF 12
#define XSLABF (BG*XROWF)         // 192 floats
#define SLABF  (WSLABF + XSLABF)  // 4416 floats
#define AG_OFF (NBUF*SLABF)       // 13248 floats
#define AGROW  33
#define SMEM_BYTES ((AG_OFF + BG*AGROW) * 4)   // 55104 B

__device__ float g_part[GX * SVOL];  // per-i-block partial s (9.7 MB)
__device__ float g_vsum[SVOL];       // running sum of squashed v's

// ---------- packed f32x2 helpers ----------
__device__ __forceinline__ unsigned long long pk2(float lo, float hi) {
    unsigned long long r;
    asm("mov.b64 %0, {%1, %2};" : "=l"(r) : "f"(lo), "f"(hi));
    return r;
}
__device__ __forceinline__ void upk2(unsigned long long v, float& lo, float& hi) {
    asm("mov.b64 {%0, %1}, %2;" : "=f"(lo), "=f"(hi) : "l"(v));
}
__device__ __forceinline__ unsigned long long fma2(unsigned long long a,
                                                   unsigned long long b,
                                                   unsigned long long c) {
    unsigned long long d;
    asm("fma.rn.f32x2 %0, %1, %2, %3;" : "=l"(d) : "l"(a), "l"(b), "l"(c));
    return d;
}

// ---------- cp.async helpers ----------
__device__ __forceinline__ void cp16(unsigned dst_smem, const void* src) {
    asm volatile("cp.async.cg.shared.global [%0], [%1], 16;"
                 :: "r"(dst_smem), "l"(src));
}
__device__ __forceinline__ void cp_commit() {
    asm volatile("cp.async.commit_group;");
}
template<int N>
__device__ __forceinline__ void cp_wait() {
    asm volatile("cp.async.wait_group %0;" :: "n"(N) : "memory");
}

// Stage one i (W tile + x column) into buffer `buf`. One commit group.
// 256 threads: W = 1024 float4 chunks (4/thread), x = 32 chunks (thr 0..31).
__device__ __forceinline__ void fill_slab(unsigned sm_addr,
                                          const float* __restrict__ W,
                                          const float* __restrict__ x,
                                          int i, int buf, int t, int bg) {
#pragma unroll
    for (int r = 0; r < 4; r++) {
        int c = t + r * 256;
        int o = c >> 5, w16 = c & 31;
        const float* src = W + ((size_t)i * OO + o) * (DD * KK) + w16 * 4;
        unsigned dst = sm_addr + (unsigned)((buf * SLABF + o * WROWF + w16 * 4) * 4);
        cp16(dst, src);
    }
    if (t < BG * 2) {
        int b = t >> 1, half = t & 1;
        const float* src = x + ((size_t)(bg * BG + b) * II + i) * DD + half * 4;
        unsigned dst = sm_addr +
            (unsigned)((buf * SLABF + WSLABF + b * XROWF + half * 4) * 4);
        cp16(dst, src);
    }
    cp_commit();
}

// Fused routing pass. 256 threads: t = o*8 + tb; thread handles b = tb, tb+8.
// Warp = 4 o x 8 tb -> W smem reads 8-way amortized.
template<bool FIRST>
__global__ __launch_bounds__(256, 2)
void pass_kernel(const float* __restrict__ x, const float* __restrict__ W) {
    extern __shared__ float sm[];
    const unsigned sm_addr = (unsigned)__cvta_generic_to_shared(sm);
    float* ag = sm + AG_OFF;

    const int t  = threadIdx.x;
    const int o  = t >> 3;
    const int tb = t & 7;
    const int bg = blockIdx.y;
    const int b0 = bg * BG + tb;
    const int b1 = b0 + 8;

    // variable i-range: block bx handles [ib, ie)  (27 or 28 i's)
    const int bx = blockIdx.x;
    const int ib = (bx * II) / GX;
    const int ie = ((bx + 1) * II) / GX;
    const int cnt = ie - ib;

    fill_slab(sm_addr, W, x, ib,     0, t, bg);
    fill_slab(sm_addr, W, x, ib + 1, 1, t, bg);

    unsigned long long Va[8], Vb[8];
    if (!FIRST) {
        const ulonglong2* vp0 =
            reinterpret_cast<const ulonglong2*>(g_vsum + ((size_t)b0 * OO + o) * KK);
        const ulonglong2* vp1 =
            reinterpret_cast<const ulonglong2*>(g_vsum + ((size_t)b1 * OO + o) * KK);
#pragma unroll
        for (int j = 0; j < 4; j++) {
            ulonglong2 q0 = vp0[j]; Va[2*j] = q0.x; Va[2*j+1] = q0.y;
            ulonglong2 q1 = vp1[j]; Vb[2*j] = q1.x; Vb[2*j+1] = q1.y;
        }
    }

    unsigned long long sa[8], sb[8];
#pragma unroll
    for (int j = 0; j < 8; j++) { sa[j] = 0ull; sb[j] = 0ull; }

    // prologue: slab 0 resident + visible
    cp_wait<1>();
    __syncthreads();

    for (int s = 0; s < cnt; s++) {
        // Invariant on entry: slab s resident & visible to all threads;
        // all warps are past their last read of slab s-1 (end barrier of s-1)
        // => safe to overwrite buffer (s+2)%3 == (s-1)%3 now.
        if (s + 2 < cnt)
            fill_slab(sm_addr, W, x, ib + s + 2, (s + 2) % NBUF, t, bg);

        const float* slab = sm + (s % NBUF) * SLABF;

        float xf0[8], xf1[8];
        {
            const float4* xr0 = reinterpret_cast<const float4*>(
                slab + WSLABF + tb * XROWF);
            const float4* xr1 = reinterpret_cast<const float4*>(
                slab + WSLABF + (tb + 8) * XROWF);
            float4 a0 = xr0[0], a1 = xr0[1];
            float4 c0 = xr1[0], c1 = xr1[1];
            xf0[0]=a0.x; xf0[1]=a0.y; xf0[2]=a0.z; xf0[3]=a0.w;
            xf0[4]=a1.x; xf0[5]=a1.y; xf0[6]=a1.z; xf0[7]=a1.w;
            xf1[0]=c0.x; xf1[1]=c0.y; xf1[2]=c0.z; xf1[3]=c0.w;
            xf1[4]=c1.x; xf1[5]=c1.y; xf1[6]=c1.z; xf1[7]=c1.w;
        }

        unsigned long long ua[8], ub[8];
#pragma unroll
        for (int j = 0; j < 8; j++) { ua[j] = 0ull; ub[j] = 0ull; }

        const float* wrow = slab + o * WROWF;
#pragma unroll
        for (int d = 0; d < DD; d++) {
            const ulonglong2* wp = reinterpret_cast<const ulonglong2*>(wrow + d * 16);
            unsigned long long xa2 = pk2(xf0[d], xf0[d]);
            unsigned long long xb2 = pk2(xf1[d], xf1[d]);
            ulonglong2 q0 = wp[0], q1 = wp[1];
            ua[0] = fma2(xa2, q0.x, ua[0]);  ub[0] = fma2(xb2, q0.x, ub[0]);
            ua[1] = fma2(xa2, q0.y, ua[1]);  ub[1] = fma2(xb2, q0.y, ub[1]);
            ua[2] = fma2(xa2, q1.x, ua[2]);  ub[2] = fma2(xb2, q1.x, ub[2]);
            ua[3] = fma2(xa2, q1.y, ua[3]);  ub[3] = fma2(xb2, q1.y, ub[3]);
            ulonglong2 q2 = wp[2], q3 = wp[3];
            ua[4] = fma2(xa2, q2.x, ua[4]);  ub[4] = fma2(xb2, q2.x, ub[4]);
            ua[5] = fma2(xa2, q2.y, ua[5]);  ub[5] = fma2(xb2, q2.y, ub[5]);
            ua[6] = fma2(xa2, q3.x, ua[6]);  ub[6] = fma2(xb2, q3.x, ub[6]);
            ua[7] = fma2(xa2, q3.y, ua[7]);  ub[7] = fma2(xb2, q3.y, ub[7]);
        }

        unsigned long long c2a, c2b;
        if (FIRST) {
            c2a = pk2(1.0f / OO, 1.0f / OO);
            c2b = c2a;
#pragma unroll
            for (int j = 0; j < 8; j++) {
                sa[j] = fma2(c2a, ua[j], sa[j]);
                sb[j] = fma2(c2b, ub[j], sb[j]);
            }
            // single end barrier: next slab resident + all reads of s done
            if (s + 2 < cnt)       cp_wait<1>();
            else if (s + 2 == cnt) cp_wait<0>();
            __syncthreads();
        } else {
            unsigned long long acca = 0ull, accb = 0ull;
#pragma unroll
            for (int j = 0; j < 8; j++) {
                acca = fma2(ua[j], Va[j], acca);
                accb = fma2(ub[j], Vb[j], accb);
            }
            float al, ah, bl2, bh;
            upk2(acca, al, ah);
            upk2(accb, bl2, bh);
            ag[tb * AGROW + o]       = al + ah;
            ag[(tb + 8) * AGROW + o] = bl2 + bh;
            __syncthreads();                 // barrier 1: agr visible

            // warp w: softmax rows w, w+8 (lane = o). No max-subtract:
            // |agr| <= |u||Vsum| = O(1), exp safe in fp32.
            {
                int w = t >> 5, lane = t & 31;
                float e0 = __expf(ag[w * AGROW + lane]);
                float e1 = __expf(ag[(w + 8) * AGROW + lane]);
                float s0 = e0, s1 = e1;
#pragma unroll
                for (int st = 16; st > 0; st >>= 1) {
                    s0 += __shfl_xor_sync(0xffffffffu, s0, st);
                    s1 += __shfl_xor_sync(0xffffffffu, s1, st);
                }
                ag[w * AGROW + lane]       = __fdividef(e0, s0);
                ag[(w + 8) * AGROW + lane] = __fdividef(e1, s1);
            }
            // overlap next-slab wait with softmax, then one merged barrier:
            // c visible + slab s+1 visible + all slab-s reads complete.
            if (s + 2 < cnt)       cp_wait<1>();
            else if (s + 2 == cnt) cp_wait<0>();
            __syncthreads();                 // barrier 2 (merged)

            float ca = ag[tb * AGROW + o];
            float cb = ag[(tb + 8) * AGROW + o];
            c2a = pk2(ca, ca);
            c2b = pk2(cb, cb);
#pragma unroll
            for (int j = 0; j < 8; j++) {
                sa[j] = fma2(c2a, ua[j], sa[j]);
                sb[j] = fma2(c2b, ub[j], sb[j]);
            }
        }
    }

    ulonglong2* p0 = reinterpret_cast<ulonglong2*>(
        g_part + ((size_t)bx * SVOL + ((size_t)b0 * OO + o) * KK));
    ulonglong2* p1 = reinterpret_cast<ulonglong2*>(
        g_part + ((size_t)bx * SVOL + ((size_t)b1 * OO + o) * KK));
    p0[0] = make_ulonglong2(sa[0], sa[1]);
    p0[1] = make_ulonglong2(sa[2], sa[3]);
    p0[2] = make_ulonglong2(sa[4], sa[5]);
    p0[3] = make_ulonglong2(sa[6], sa[7]);
    p1[0] = make_ulonglong2(sb[0], sb[1]);
    p1[1] = make_ulonglong2(sb[2], sb[3]);
    p1[2] = make_ulonglong2(sb[4], sb[5]);
    p1[3] = make_ulonglong2(sb[6], sb[7]);
}

// Reduce partials over GX=74 slabs (4 chains + 2 tail), squash over K=16.
// phase 0: vsum = v ; phase 1: vsum += v ; phase 2: out = v
__global__ void squash_kernel(float* __restrict__ out, int phase) {
    int idx = blockIdx.x * 256 + threadIdx.x;   // (b*O+o)*K + k
    float a0 = 0.f, a1 = 0.f, a2 = 0.f, a3 = 0.f;
#pragma unroll
    for (int p = 0; p + 4 <= GX; p += 4) {      // p = 0..68, covers 0..71
        a0 += g_part[(size_t)(p + 0) * SVOL + idx];
        a1 += g_part[(size_t)(p + 1) * SVOL + idx];
        a2 += g_part[(size_t)(p + 2) * SVOL + idx];
        a3 += g_part[(size_t)(p + 3) * SVOL + idx];
    }
    a0 += g_part[(size_t)72 * SVOL + idx];
    a1 += g_part[(size_t)73 * SVOL + idx];
    float s = (a0 + a1) + (a2 + a3);

    float s2 = s * s;
    s2 += __shfl_xor_sync(0xffffffffu, s2, 1);
    s2 += __shfl_xor_sync(0xffffffffu, s2, 2);
    s2 += __shfl_xor_sync(0xffffffffu, s2, 4);
    s2 += __shfl_xor_sync(0xffffffffu, s2, 8);

    float scale = s2 / ((1.0f + s2) * sqrtf(s2 + 1e-7f));
    float v = scale * s;

    if (phase == 0)      g_vsum[idx] = v;
    else if (phase == 1) g_vsum[idx] += v;
    else                 out[idx] = v;
}

// No-op: keeps ncu's -s 5 -c 1 capture window on pass#3 (softmax pass).
__global__ void dummy_kernel() {}

extern "C" void kernel_launch(void* const* d_in, const int* in_sizes, int n_in,
                              void* d_out, int out_size) {
    const float* a0 = (const float*)d_in[0];
    const float* a1 = (const float*)d_in[1];
    const float* x;
    const float* W;
    if (in_sizes[0] == BB * II * DD) { x = a0; W = a1; }
    else                             { x = a1; W = a0; }
    float* out = (float*)d_out;

    cudaFuncSetAttribute(pass_kernel<true>,
                         cudaFuncAttributeMaxDynamicSharedMemorySize, SMEM_BYTES);
    cudaFuncSetAttribute(pass_kernel<false>,
                         cudaFuncAttributeMaxDynamicSharedMemorySize, SMEM_BYTES);

    dim3 pg(GX, BB / BG);          // (74, 4) = 296 blocks = 148 SMs x 2
    const int rb = SVOL / 256;     // 128 blocks for squash

    dummy_kernel<<<1, 32>>>();                           // #1 (aligns capture)

    pass_kernel<true><<<pg, 256, SMEM_BYTES>>>(x, W);    // #2: s0 (uniform c)
    squash_kernel<<<rb, 256>>>(out, 0);                  // #3: v0 -> Vsum

    pass_kernel<false><<<pg, 256, SMEM_BYTES>>>(x, W);   // #4: s1 (vs v0)
    squash_kernel<<<rb, 256>>>(out, 1);                  // #5: Vsum += v1

    pass_kernel<false><<<pg, 256, SMEM_BYTES>>>(x, W);   // #6: s2 (profiled)
    squash_kernel<<<rb, 256>>>(out, 2);                  // #7: v2 = output
}

// round 11
// speedup vs baseline: 2.0091x; 1.5096x over previous
#include <cuda_runtime.h>

// CapsuleLayer: x[B,I,D] fp32, W[I,O,D,K] fp32 -> v[B,O,K] fp32
// B=64, I=2048, D=8, O=32, K=16, 3 routing rounds.
// Routing logits linear in v => each round is one fused sweep over i.
// Round 11: exact R8 pass structure (best measured: 147.7us) restored.
// R10's wall-clock regression showed *better* per-cycle metrics (fma 39%,
// issue 41.3%) -> attributed to a session clock-state change, not structure.
// This round re-establishes the R8 baseline + squash 8-chain MLP fix.

#define BB 64
#define II 2048
#define DD 8
#define OO 32
#define KK 16
#define BG 16            // b's per block (2 per thread)
#define GX 74            // i-blocks; grid = 74 x 4 = 296 = 148 SMs x 2
#define NBUF 3
#define SVOL (BB*OO*KK)  // 32768

#define WROWF 132                 // padded floats per o-row
#define WSLABF (OO*WROWF)         // 4224 floats (one i)
#define XROWF 12
#define XSLABF (BG*XROWF)         // 192 floats
#define SLABF  (WSLABF + XSLABF)  // 4416 floats
#define AG_OFF (NBUF*SLABF)       // 13248 floats
#define AGROW  33
#define SMEM_BYTES ((AG_OFF + BG*AGROW) * 4)   // 55104 B

__device__ float g_part[GX * SVOL];  // per-i-block partial s (9.7 MB)
__device__ float g_vsum[SVOL];       // running sum of squashed v's

// ---------- packed f32x2 helpers ----------
__device__ __forceinline__ unsigned long long pk2(float lo, float hi) {
    unsigned long long r;
    asm("mov.b64 %0, {%1, %2};" : "=l"(r) : "f"(lo), "f"(hi));
    return r;
}
__device__ __forceinline__ void upk2(unsigned long long v, float& lo, float& hi) {
    asm("mov.b64 {%0, %1}, %2;" : "=f"(lo), "=f"(hi) : "l"(v));
}
__device__ __forceinline__ unsigned long long fma2(unsigned long long a,
                                                   unsigned long long b,
                                                   unsigned long long c) {
    unsigned long long d;
    asm("fma.rn.f32x2 %0, %1, %2, %3;" : "=l"(d) : "l"(a), "l"(b), "l"(c));
    return d;
}

// ---------- cp.async helpers ----------
__device__ __forceinline__ void cp16(unsigned dst_smem, const void* src) {
    asm volatile("cp.async.cg.shared.global [%0], [%1], 16;"
                 :: "r"(dst_smem), "l"(src));
}
__device__ __forceinline__ void cp_commit() {
    asm volatile("cp.async.commit_group;");
}
template<int N>
__device__ __forceinline__ void cp_wait() {
    asm volatile("cp.async.wait_group %0;" :: "n"(N) : "memory");
}

// Stage one i (W tile + x column) into buffer `buf`. One commit group.
// 256 threads: W = 1024 float4 chunks (4/thread), x = 32 chunks (thr 0..31).
__device__ __forceinline__ void fill_slab(unsigned sm_addr,
                                          const float* __restrict__ W,
                                          const float* __restrict__ x,
                                          int i, int buf, int t, int bg) {
#pragma unroll
    for (int r = 0; r < 4; r++) {
        int c = t + r * 256;
        int o = c >> 5, w16 = c & 31;
        const float* src = W + ((size_t)i * OO + o) * (DD * KK) + w16 * 4;
        unsigned dst = sm_addr + (unsigned)((buf * SLABF + o * WROWF + w16 * 4) * 4);
        cp16(dst, src);
    }
    if (t < BG * 2) {
        int b = t >> 1, half = t & 1;
        const float* src = x + ((size_t)(bg * BG + b) * II + i) * DD + half * 4;
        unsigned dst = sm_addr +
            (unsigned)((buf * SLABF + WSLABF + b * XROWF + half * 4) * 4);
        cp16(dst, src);
    }
    cp_commit();
}

// Fused routing pass. 256 threads: t = o*8 + tb; thread handles b = tb, tb+8.
// Warp = 4 o x 8 tb -> W smem reads 8-way amortized.
template<bool FIRST>
__global__ __launch_bounds__(256, 2)
void pass_kernel(const float* __restrict__ x, const float* __restrict__ W) {
    extern __shared__ float sm[];
    const unsigned sm_addr = (unsigned)__cvta_generic_to_shared(sm);
    float* ag = sm + AG_OFF;

    const int t  = threadIdx.x;
    const int o  = t >> 3;
    const int tb = t & 7;
    const int bg = blockIdx.y;
    const int b0 = bg * BG + tb;
    const int b1 = b0 + 8;

    // variable i-range: block bx handles [ib, ie)  (27 or 28 i's)
    const int bx = blockIdx.x;
    const int ib = (bx * II) / GX;
    const int ie = ((bx + 1) * II) / GX;
    const int cnt = ie - ib;

    fill_slab(sm_addr, W, x, ib,     0, t, bg);
    fill_slab(sm_addr, W, x, ib + 1, 1, t, bg);

    unsigned long long Va[8], Vb[8];
    if (!FIRST) {
        const ulonglong2* vp0 =
            reinterpret_cast<const ulonglong2*>(g_vsum + ((size_t)b0 * OO + o) * KK);
        const ulonglong2* vp1 =
            reinterpret_cast<const ulonglong2*>(g_vsum + ((size_t)b1 * OO + o) * KK);
#pragma unroll
        for (int j = 0; j < 4; j++) {
            ulonglong2 q0 = vp0[j]; Va[2*j] = q0.x; Va[2*j+1] = q0.y;
            ulonglong2 q1 = vp1[j]; Vb[2*j] = q1.x; Vb[2*j+1] = q1.y;
        }
    }

    unsigned long long sa[8], sb[8];
#pragma unroll
    for (int j = 0; j < 8; j++) { sa[j] = 0ull; sb[j] = 0ull; }

    for (int s = 0; s < cnt; s++) {
        if (s + 1 < cnt) cp_wait<1>(); else cp_wait<0>();
        __syncthreads();   // slab s resident; all warps done with slab s-1
        if (s + 2 < cnt)
            fill_slab(sm_addr, W, x, ib + s + 2, (s + 2) % NBUF, t, bg);

        const float* slab = sm + (s % NBUF) * SLABF;

        float xf0[8], xf1[8];
        {
            const float4* xr0 = reinterpret_cast<const float4*>(
                slab + WSLABF + tb * XROWF);
            const float4* xr1 = reinterpret_cast<const float4*>(
                slab + WSLABF + (tb + 8) * XROWF);
            float4 a0 = xr0[0], a1 = xr0[1];
            float4 c0 = xr1[0], c1 = xr1[1];
            xf0[0]=a0.x; xf0[1]=a0.y; xf0[2]=a0.z; xf0[3]=a0.w;
            xf0[4]=a1.x; xf0[5]=a1.y; xf0[6]=a1.z; xf0[7]=a1.w;
            xf1[0]=c0.x; xf1[1]=c0.y; xf1[2]=c0.z; xf1[3]=c0.w;
            xf1[4]=c1.x; xf1[5]=c1.y; xf1[6]=c1.z; xf1[7]=c1.w;
        }

        unsigned long long ua[8], ub[8];
#pragma unroll
        for (int j = 0; j < 8; j++) { ua[j] = 0ull; ub[j] = 0ull; }

        const float* wrow = slab + o * WROWF;
#pragma unroll
        for (int d = 0; d < DD; d++) {
            const ulonglong2* wp = reinterpret_cast<const ulonglong2*>(wrow + d * 16);
            unsigned long long xa2 = pk2(xf0[d], xf0[d]);
            unsigned long long xb2 = pk2(xf1[d], xf1[d]);
            ulonglong2 q0 = wp[0], q1 = wp[1];
            ua[0] = fma2(xa2, q0.x, ua[0]);  ub[0] = fma2(xb2, q0.x, ub[0]);
            ua[1] = fma2(xa2, q0.y, ua[1]);  ub[1] = fma2(xb2, q0.y, ub[1]);
            ua[2] = fma2(xa2, q1.x, ua[2]);  ub[2] = fma2(xb2, q1.x, ub[2]);
            ua[3] = fma2(xa2, q1.y, ua[3]);  ub[3] = fma2(xb2, q1.y, ub[3]);
            ulonglong2 q2 = wp[2], q3 = wp[3];
            ua[4] = fma2(xa2, q2.x, ua[4]);  ub[4] = fma2(xb2, q2.x, ub[4]);
            ua[5] = fma2(xa2, q2.y, ua[5]);  ub[5] = fma2(xb2, q2.y, ub[5]);
            ua[6] = fma2(xa2, q3.x, ua[6]);  ub[6] = fma2(xb2, q3.x, ub[6]);
            ua[7] = fma2(xa2, q3.y, ua[7]);  ub[7] = fma2(xb2, q3.y, ub[7]);
        }

        unsigned long long c2a, c2b;
        if (FIRST) {
            c2a = pk2(1.0f / OO, 1.0f / OO);
            c2b = c2a;
        } else {
            unsigned long long acca = 0ull, accb = 0ull;
#pragma unroll
            for (int j = 0; j < 8; j++) {
                acca = fma2(ua[j], Va[j], acca);
                accb = fma2(ub[j], Vb[j], accb);
            }
            float al, ah, bl2, bh;
            upk2(acca, al, ah);
            upk2(accb, bl2, bh);
            ag[tb * AGROW + o]       = al + ah;
            ag[(tb + 8) * AGROW + o] = bl2 + bh;
            __syncthreads();                 // barrier 1: agr visible

            // warp w: softmax rows w, w+8 (lane = o). No max-subtract:
            // |agr| <= |u||Vsum| = O(1), exp safe in fp32.
            {
                int w = t >> 5, lane = t & 31;
                float e0 = __expf(ag[w * AGROW + lane]);
                float e1 = __expf(ag[(w + 8) * AGROW + lane]);
                float s0 = e0, s1 = e1;
#pragma unroll
                for (int st = 16; st > 0; st >>= 1) {
                    s0 += __shfl_xor_sync(0xffffffffu, s0, st);
                    s1 += __shfl_xor_sync(0xffffffffu, s1, st);
                }
                ag[w * AGROW + lane]       = __fdividef(e0, s0);
                ag[(w + 8) * AGROW + lane] = __fdividef(e1, s1);
            }
            __syncthreads();                 // barrier 2: c visible

            float ca = ag[tb * AGROW + o];
            float cb = ag[(tb + 8) * AGROW + o];
            c2a = pk2(ca, ca);
            c2b = pk2(cb, cb);
        }

#pragma unroll
        for (int j = 0; j < 8; j++) {
            sa[j] = fma2(c2a, ua[j], sa[j]);
            sb[j] = fma2(c2b, ub[j], sb[j]);
        }
    }

    ulonglong2* p0 = reinterpret_cast<ulonglong2*>(
        g_part + ((size_t)bx * SVOL + ((size_t)b0 * OO + o) * KK));
    ulonglong2* p1 = reinterpret_cast<ulonglong2*>(
        g_part + ((size_t)bx * SVOL + ((size_t)b1 * OO + o) * KK));
    p0[0] = make_ulonglong2(sa[0], sa[1]);
    p0[1] = make_ulonglong2(sa[2], sa[3]);
    p0[2] = make_ulonglong2(sa[4], sa[5]);
    p0[3] = make_ulonglong2(sa[6], sa[7]);
    p1[0] = make_ulonglong2(sb[0], sb[1]);
    p1[1] = make_ulonglong2(sb[2], sb[3]);
    p1[2] = make_ulonglong2(sb[4], sb[5]);
    p1[3] = make_ulonglong2(sb[6], sb[7]);
}

// Reduce partials over GX=74 slabs (8 independent chains for MLP), squash K=16.
// phase 0: vsum = v ; phase 1: vsum += v ; phase 2: out = v
__global__ void squash_kernel(float* __restrict__ out, int phase) {
    int idx = blockIdx.x * 256 + threadIdx.x;   // (b*O+o)*K + k
    float a0 = 0.f, a1 = 0.f, a2 = 0.f, a3 = 0.f;
    float a4 = 0.f, a5 = 0.f, a6 = 0.f, a7 = 0.f;
#pragma unroll
    for (int p = 0; p + 8 <= GX; p += 8) {      // p = 0..64, covers 0..71
        a0 += g_part[(size_t)(p + 0) * SVOL + idx];
        a1 += g_part[(size_t)(p + 1) * SVOL + idx];
        a2 += g_part[(size_t)(p + 2) * SVOL + idx];
        a3 += g_part[(size_t)(p + 3) * SVOL + idx];
        a4 += g_part[(size_t)(p + 4) * SVOL + idx];
        a5 += g_part[(size_t)(p + 5) * SVOL + idx];
        a6 += g_part[(size_t)(p + 6) * SVOL + idx];
        a7 += g_part[(size_t)(p + 7) * SVOL + idx];
    }
    a0 += g_part[(size_t)72 * SVOL + idx];
    a1 += g_part[(size_t)73 * SVOL + idx];
    float s = ((a0 + a1) + (a2 + a3)) + ((a4 + a5) + (a6 + a7));

    float s2 = s * s;
    s2 += __shfl_xor_sync(0xffffffffu, s2, 1);
    s2 += __shfl_xor_sync(0xffffffffu, s2, 2);
    s2 += __shfl_xor_sync(0xffffffffu, s2, 4);
    s2 += __shfl_xor_sync(0xffffffffu, s2, 8);

    float scale = s2 / ((1.0f + s2) * sqrtf(s2 + 1e-7f));
    float v = scale * s;

    if (phase == 0)      g_vsum[idx] = v;
    else if (phase == 1) g_vsum[idx] += v;
    else                 out[idx] = v;
}

// No-op: keeps ncu's -s 5 -c 1 capture window on pass#3 (softmax pass).
__global__ void dummy_kernel() {}

extern "C" void kernel_launch(void* const* d_in, const int* in_sizes, int n_in,
                              void* d_out, int out_size) {
    const float* a0 = (const float*)d_in[0];
    const float* a1 = (const float*)d_in[1];
    const float* x;
    const float* W;
    if (in_sizes[0] == BB * II * DD) { x = a0; W = a1; }
    else                             { x = a1; W = a0; }
    float* out = (float*)d_out;

    cudaFuncSetAttribute(pass_kernel<true>,
                         cudaFuncAttributeMaxDynamicSharedMemorySize, SMEM_BYTES);
    cudaFuncSetAttribute(pass_kernel<false>,
                         cudaFuncAttributeMaxDynamicSharedMemorySize, SMEM_BYTES);

    dim3 pg(GX, BB / BG);          // (74, 4) = 296 blocks = 148 SMs x 2
    const int rb = SVOL / 256;     // 128 blocks for squash

    dummy_kernel<<<1, 32>>>();                           // #1 (aligns capture)

    pass_kernel<true><<<pg, 256, SMEM_BYTES>>>(x, W);    // #2: s0 (uniform c)
    squash_kernel<<<rb, 256>>>(out, 0);                  // #3: v0 -> Vsum

    pass_kernel<false><<<pg, 256, SMEM_BYTES>>>(x, W);   // #4: s1 (vs v0)
    squash_kernel<<<rb, 256>>>(out, 1);                  // #5: Vsum += v1

    pass_kernel<false><<<pg, 256, SMEM_BYTES>>>(x, W);   // #6: s2 (profiled)
    squash_kernel<<<rb, 256>>>(out, 2);                  // #7: v2 = output
}